// round 5
// baseline (speedup 1.0000x reference)
#include <cuda_runtime.h>

// LayerNorm backward fused: golden_x [B,S,H], golden_gamma [H], golden_beta [H]
// B=4, S=4096, H=2048, fp32. Output layout: [x | gamma | beta] concatenated.
// R4: 512 threads (4 cols/thread), grid=148 persistent, depth-2 register
//     prefetch of dy/x1/x2 via unroll-2 rotating buffers; dsum loaded
//     in-iteration; single-barrier double-buffered 16-warp reduction.

#define HF 2048
#define ROWS 16384           // B*S
#define THREADS 512
#define GRID 148             // 1 persistent CTA per SM

__global__ void zero_param_grads(float* __restrict__ out) {
    int i = blockIdx.x * blockDim.x + threadIdx.x;
    if (i < 2 * HF) out[(size_t)ROWS * HF + i] = 0.0f;
}

__global__ __launch_bounds__(THREADS, 1) void ln_bwd_kernel(
    const float* __restrict__ dy,
    const float* __restrict__ x1,
    const float* __restrict__ x2,
    const float* __restrict__ rstd,
    const float* __restrict__ mean,
    const float* __restrict__ gamma,
    const float* __restrict__ dsum,
    float* __restrict__ out)
{
    __shared__ float red[2][3][16];

    const int tid  = threadIdx.x;
    const int lane = tid & 31;
    const int wid  = tid >> 5;          // 0..15
    const int bid  = blockIdx.x;
    const int c    = 4 * tid;           // thread owns columns [c, c+4)

    const float4 g = *(const float4*)(gamma + c);
    float ag[4] = {0.f, 0.f, 0.f, 0.f};
    float ab[4] = {0.f, 0.f, 0.f, 0.f};
    const float inv_d = 1.0f / (float)HF;

    // ---- rotating prefetch buffers (depth 2) ----
    float4 Ad, Ax, Ay; float Amu = 0.f, Ars = 0.f;
    float4 Bd, Bx, By; float Bmu = 0.f, Brs = 0.f;

    #define LOADROW(row, D, X, Y, MU, RS)                                   \
        if ((row) < ROWS) {                                                 \
            const size_t _b = (size_t)(row) * HF;                           \
            D  = __ldcs((const float4*)(dy + _b + c));                      \
            X  = __ldcs((const float4*)(x1 + _b + c));                      \
            Y  = __ldcs((const float4*)(x2 + _b + c));                      \
            MU = __ldcs(mean + (row));                                      \
            RS = __ldcs(rstd + (row));                                      \
        }

    #define PROCESS(row, D, X, Y, MU, RS, PAR)                              \
    {                                                                       \
        const size_t base = (size_t)(row) * HF;                             \
        const float4 ds = __ldcs((const float4*)(dsum + base + c));         \
        const float mu = (MU), rs = (RS);                                   \
        float dyv[4] = {(D).x, (D).y, (D).z, (D).w};                        \
        float xh[4]  = {(X).x + (Y).x - mu, (X).y + (Y).y - mu,             \
                        (X).z + (Y).z - mu, (X).w + (Y).w - mu};            \
        float gv[4]  = {g.x, g.y, g.z, g.w};                                \
        float s1 = 0.f, s2 = 0.f, s3 = 0.f;                                 \
        _Pragma("unroll")                                                   \
        for (int k = 0; k < 4; k++) {                                       \
            const float pdxl = dyv[k] * gv[k];                              \
            s1 = fmaf(pdxl, xh[k], s1);                                     \
            s2 += pdxl;                                                     \
            s3 += xh[k];                                                    \
        }                                                                   \
        _Pragma("unroll")                                                   \
        for (int off = 16; off > 0; off >>= 1) {                            \
            s1 += __shfl_xor_sync(0xFFFFFFFFu, s1, off);                    \
            s2 += __shfl_xor_sync(0xFFFFFFFFu, s2, off);                    \
            s3 += __shfl_xor_sync(0xFFFFFFFFu, s3, off);                    \
        }                                                                   \
        if (lane == 0) {                                                    \
            red[PAR][0][wid] = s1;                                          \
            red[PAR][1][wid] = s2;                                          \
            red[PAR][2][wid] = s3;                                          \
        }                                                                   \
        __syncthreads();                                                    \
        float t1 = 0.f, t2 = 0.f, t3 = 0.f;                                 \
        _Pragma("unroll")                                                   \
        for (int w = 0; w < 16; w++) {                                      \
            t1 += red[PAR][0][w];                                           \
            t2 += red[PAR][1][w];                                           \
            t3 += red[PAR][2][w];                                           \
        }                                                                   \
        const float rs3     = rs * rs * rs;                                 \
        const float pd_var  = -0.5f * t1 * rs3;                             \
        const float pd_mean = -t2 * rs + pd_var * (-2.0f * inv_d) * t3;     \
        const float coef    = pd_var * (2.0f * inv_d);                      \
        const float cmean   = pd_mean * inv_d;                              \
        float ov[4];                                                        \
        _Pragma("unroll")                                                   \
        for (int k = 0; k < 4; k++) {                                       \
            const float pdxl = dyv[k] * gv[k];                              \
            ov[k] = fmaf(pdxl, rs, fmaf(coef, xh[k], cmean));               \
            ag[k] = fmaf(dyv[k] * xh[k], rs, ag[k]);                        \
            ab[k] += dyv[k];                                                \
        }                                                                   \
        ov[0] += ds.x; ov[1] += ds.y; ov[2] += ds.z; ov[3] += ds.w;         \
        __stcs((float4*)(out + base + c),                                   \
               make_float4(ov[0], ov[1], ov[2], ov[3]));                    \
    }

    // ---- prologue: rows bid and bid+GRID in flight ----
    LOADROW(bid,        Ad, Ax, Ay, Amu, Ars);
    LOADROW(bid + GRID, Bd, Bx, By, Bmu, Brs);

    int it = 0;
    for (int r = bid; r < ROWS; r += 2 * GRID) {
        // issue row r+2G BEFORE consuming row r -> loads in flight through
        // the barrier, epilogue and store
        float4 Td, Tx, Ty; float Tmu = 0.f, Trs = 0.f;
        LOADROW(r + 2 * GRID, Td, Tx, Ty, Tmu, Trs);

        PROCESS(r, Ad, Ax, Ay, Amu, Ars, (it & 1)); it++;
        Ad = Td; Ax = Tx; Ay = Ty; Amu = Tmu; Ars = Trs;

        float4 Ud, Ux, Uy; float Umu = 0.f, Urs = 0.f;
        LOADROW(r + 3 * GRID, Ud, Ux, Uy, Umu, Urs);

        if (r + GRID < ROWS) {
            PROCESS(r + GRID, Bd, Bx, By, Bmu, Brs, (it & 1)); it++;
        }
        Bd = Ud; Bx = Ux; By = Uy; Bmu = Umu; Brs = Urs;
    }

    // flush dgamma/dbeta partials: 148 CTAs * 4096 atomics -> negligible
    float* gout = out + (size_t)ROWS * HF;
    float* bout = gout + HF;
    #pragma unroll
    for (int k = 0; k < 4; k++) {
        atomicAdd(gout + c + k, ag[k]);
        atomicAdd(bout + c + k, ab[k]);
    }
}

extern "C" void kernel_launch(void* const* d_in, const int* in_sizes, int n_in,
                              void* d_out, int out_size) {
    const float* dy    = (const float*)d_in[0];
    const float* x1    = (const float*)d_in[1];
    const float* x2    = (const float*)d_in[2];
    const float* rstd  = (const float*)d_in[3];
    const float* mean  = (const float*)d_in[4];
    const float* gamma = (const float*)d_in[5];
    const float* dsum  = (const float*)d_in[6];
    float* out = (float*)d_out;

    zero_param_grads<<<(2 * HF + 255) / 256, 256>>>(out);
    ln_bwd_kernel<<<GRID, THREADS>>>(dy, x1, x2, rstd, mean, gamma, dsum, out);
}

// round 6
// speedup vs baseline: 1.2766x; 1.2766x over previous
#include <cuda_runtime.h>

// LayerNorm backward fused: golden_x [B,S,H], golden_gamma [H], golden_beta [H]
// B=4, S=4096, H=2048, fp32. Output layout: [x | gamma | beta] concatenated.
// R5: R2 structure (2 CTAs/SM x 256 thr, 8 cols/thread) with distance-2
//     double-buffered register prefetch of dy/x1/x2 (2 buffer sets, consumed
//     into locals at iteration top). dsum/mean/rstd loaded in-iteration.

#define HF 2048
#define ROWS 16384           // B*S
#define THREADS 256
#define GRID 296             // 148 SMs * 2 CTAs/SM

__global__ void zero_param_grads(float* __restrict__ out) {
    int i = blockIdx.x * blockDim.x + threadIdx.x;
    if (i < 2 * HF) out[(size_t)ROWS * HF + i] = 0.0f;
}

__global__ __launch_bounds__(THREADS, 2) void ln_bwd_kernel(
    const float* __restrict__ dy,
    const float* __restrict__ x1,
    const float* __restrict__ x2,
    const float* __restrict__ rstd,
    const float* __restrict__ mean,
    const float* __restrict__ gamma,
    const float* __restrict__ dsum,
    float* __restrict__ out)
{
    __shared__ float red[2][3][8];

    const int tid  = threadIdx.x;
    const int lane = tid & 31;
    const int wid  = tid >> 5;
    const int bid  = blockIdx.x;

    const int c0 = 4 * tid;          // 0..1020
    const int c1 = c0 + HF / 2;      // 1024..2044

    const float4 g0 = *(const float4*)(gamma + c0);
    const float4 g1 = *(const float4*)(gamma + c1);
    float gv[8] = {g0.x, g0.y, g0.z, g0.w, g1.x, g1.y, g1.z, g1.w};

    float ag[8] = {0.f, 0.f, 0.f, 0.f, 0.f, 0.f, 0.f, 0.f};
    float ab[8] = {0.f, 0.f, 0.f, 0.f, 0.f, 0.f, 0.f, 0.f};

    const float inv_d = 1.0f / (float)HF;

    // ---- two register buffer sets: dy, x1, x2 (+ mean/rstd scalars) ----
    float4 Ady0, Ady1, Aa0, Aa1, Ab0, Ab1; float Amu = 0.f, Ars = 0.f;
    float4 Bdy0, Bdy1, Ba0, Ba1, Bb0, Bb1; float Bmu = 0.f, Brs = 0.f;

    #define LOADBUF(P, row)                                                  \
        if ((row) < ROWS) {                                                  \
            const size_t _b = (size_t)(row) * HF;                            \
            P##dy0 = __ldcs((const float4*)(dy + _b + c0));                  \
            P##dy1 = __ldcs((const float4*)(dy + _b + c1));                  \
            P##a0  = __ldcs((const float4*)(x1 + _b + c0));                  \
            P##a1  = __ldcs((const float4*)(x1 + _b + c1));                  \
            P##b0  = __ldcs((const float4*)(x2 + _b + c0));                  \
            P##b1  = __ldcs((const float4*)(x2 + _b + c1));                  \
            P##mu  = __ldcs(mean + (row));                                   \
            P##rs  = __ldcs(rstd + (row));                                   \
        }

    // Consume buffer P (row `row`), refill P for row `nrow`, do full row work.
    #define STEP(P, row, nrow, PAR)                                          \
    {                                                                        \
        const size_t base = (size_t)(row) * HF;                              \
        /* consume buffer into locals (frees P for the refill below) */      \
        float dyv[8] = {P##dy0.x, P##dy0.y, P##dy0.z, P##dy0.w,              \
                        P##dy1.x, P##dy1.y, P##dy1.z, P##dy1.w};             \
        const float mu = P##mu;                                              \
        const float rs = P##rs;                                              \
        float xh[8]  = {P##a0.x + P##b0.x - mu, P##a0.y + P##b0.y - mu,      \
                        P##a0.z + P##b0.z - mu, P##a0.w + P##b0.w - mu,      \
                        P##a1.x + P##b1.x - mu, P##a1.y + P##b1.y - mu,      \
                        P##a1.z + P##b1.z - mu, P##a1.w + P##b1.w - mu};     \
        /* dsum for THIS row: issued now, consumed post-barrier */           \
        const float4 ds0 = __ldcs((const float4*)(dsum + base + c0));        \
        const float4 ds1 = __ldcs((const float4*)(dsum + base + c1));        \
        /* refill buffer: distance-2 prefetch */                             \
        LOADBUF(P, nrow);                                                    \
        /* local partial sums */                                             \
        float s1 = 0.f, s2 = 0.f, s3 = 0.f;                                  \
        _Pragma("unroll")                                                    \
        for (int k = 0; k < 8; k++) {                                        \
            const float pdxl = dyv[k] * gv[k];                               \
            s1 = fmaf(pdxl, xh[k], s1);                                      \
            s2 += pdxl;                                                      \
            s3 += xh[k];                                                     \
        }                                                                    \
        _Pragma("unroll")                                                    \
        for (int off = 16; off > 0; off >>= 1) {                             \
            s1 += __shfl_xor_sync(0xFFFFFFFFu, s1, off);                     \
            s2 += __shfl_xor_sync(0xFFFFFFFFu, s2, off);                     \
            s3 += __shfl_xor_sync(0xFFFFFFFFu, s3, off);                     \
        }                                                                    \
        if (lane == 0) {                                                     \
            red[PAR][0][wid] = s1;                                           \
            red[PAR][1][wid] = s2;                                           \
            red[PAR][2][wid] = s3;                                           \
        }                                                                    \
        __syncthreads();                                                     \
        float t1 = 0.f, t2 = 0.f, t3 = 0.f;                                  \
        _Pragma("unroll")                                                    \
        for (int w = 0; w < 8; w++) {                                        \
            t1 += red[PAR][0][w];                                            \
            t2 += red[PAR][1][w];                                            \
            t3 += red[PAR][2][w];                                            \
        }                                                                    \
        const float rs3     = rs * rs * rs;                                  \
        const float pd_var  = -0.5f * t1 * rs3;                              \
        const float pd_mean = -t2 * rs + pd_var * (-2.0f * inv_d) * t3;      \
        const float coef    = pd_var * (2.0f * inv_d);                       \
        const float cmean   = pd_mean * inv_d;                               \
        float ov[8];                                                         \
        _Pragma("unroll")                                                    \
        for (int k = 0; k < 8; k++) {                                        \
            const float pdxl = dyv[k] * gv[k];                               \
            ov[k] = fmaf(pdxl, rs, fmaf(coef, xh[k], cmean));                \
            ag[k] = fmaf(dyv[k] * xh[k], rs, ag[k]);                         \
            ab[k] += dyv[k];                                                 \
        }                                                                    \
        ov[0] += ds0.x; ov[1] += ds0.y; ov[2] += ds0.z; ov[3] += ds0.w;      \
        ov[4] += ds1.x; ov[5] += ds1.y; ov[6] += ds1.z; ov[7] += ds1.w;      \
        __stcs((float4*)(out + base + c0),                                   \
               make_float4(ov[0], ov[1], ov[2], ov[3]));                     \
        __stcs((float4*)(out + base + c1),                                   \
               make_float4(ov[4], ov[5], ov[6], ov[7]));                     \
    }

    // ---- prologue: rows bid (A) and bid+GRID (B) in flight ----
    LOADBUF(A, bid);
    LOADBUF(B, bid + GRID);

    int par = 0;
    for (int r = bid; r < ROWS; r += 2 * GRID) {
        STEP(A, r, r + 2 * GRID, par); par ^= 1;
        if (r + GRID < ROWS) {
            STEP(B, r + GRID, r + 3 * GRID, par); par ^= 1;
        }
    }

    // flush dgamma/dbeta partials: 296 CTAs * 4096 atomics -> negligible
    float* gout = out + (size_t)ROWS * HF;
    float* bout = gout + HF;
    #pragma unroll
    for (int k = 0; k < 4; k++) {
        atomicAdd(gout + c0 + k, ag[k]);
        atomicAdd(gout + c1 + k, ag[4 + k]);
        atomicAdd(bout + c0 + k, ab[k]);
        atomicAdd(bout + c1 + k, ab[4 + k]);
    }
}

extern "C" void kernel_launch(void* const* d_in, const int* in_sizes, int n_in,
                              void* d_out, int out_size) {
    const float* dy    = (const float*)d_in[0];
    const float* x1    = (const float*)d_in[1];
    const float* x2    = (const float*)d_in[2];
    const float* rstd  = (const float*)d_in[3];
    const float* mean  = (const float*)d_in[4];
    const float* gamma = (const float*)d_in[5];
    const float* dsum  = (const float*)d_in[6];
    float* out = (float*)d_out;

    zero_param_grads<<<(2 * HF + 255) / 256, 256>>>(out);
    ln_bwd_kernel<<<GRID, THREADS>>>(dy, x1, x2, rstd, mean, gamma, dsum, out);
}